// round 10
// baseline (speedup 1.0000x reference)
#include <cuda_runtime.h>
#include <cuda_bf16.h>
#include <cstdint>

// HashGridEncoding R10: fixed-capacity spatial binning (no sort/scan/compact)
// + level-major bin-coherent main kernel.
// Bins = 16^3 = 4096 (== level-4 cells), capacity 128 (avg 64). Warp lanes all
// share one l4 cell -> l0..l4 gathers become near-broadcast; l5/l6 heavily
// sector-shared; l7/l8 compulsory. Overflow (P~1e-13 here) handled by a tiny
// fallback kernel for unconditional correctness. Counters self-reset.

#define NUM_LEVELS 9
#define NBINS 4096
#define CAP   128
#define PMAX  262144

__device__ int    g_cnt[NBINS];          // zeroed at start; k_main resets
__device__ float4 g_slot[NBINS * CAP];   // {x, y, z, bitcast(id)}
__device__ int    g_over_cnt;            // k_over resets
__device__ int    g_over_ids[PMAX];

// ---------------- binning ----------------
__device__ __forceinline__ void place(float px, float py, float pz, int id)
{
    int bx = min(15, max(0, (int)((px + 1.0f) * 8.0f)));
    int by = min(15, max(0, (int)((py + 1.0f) * 8.0f)));
    int bz = min(15, max(0, (int)((pz + 1.0f) * 8.0f)));
    int b  = bx | (by << 4) | (bz << 8);
    int r  = atomicAdd(&g_cnt[b], 1);
    if (r < CAP) {
        g_slot[b * CAP + r] = make_float4(px, py, pz, __int_as_float(id));
    } else {
        int o = atomicAdd(&g_over_cnt, 1);
        g_over_ids[o] = id;
    }
}

__global__ void k_bin(const float4* __restrict__ x4, int P)
{
    int t = blockIdx.x * blockDim.x + threadIdx.x;
    int p0 = t * 4;
    if (p0 >= P) return;
    float4 a = x4[t * 3 + 0];
    float4 b = x4[t * 3 + 1];
    float4 c = x4[t * 3 + 2];
    place(a.x, a.y, a.z, p0);
    if (p0 + 1 < P) place(a.w, b.x, b.y, p0 + 1);
    if (p0 + 2 < P) place(b.z, b.w, c.x, p0 + 2);
    if (p0 + 3 < P) place(c.y, c.z, c.w, p0 + 3);
}

// ---------------- interpolation core ----------------
__device__ __forceinline__ void load_pair(const float4* __restrict__ t4, int b,
                                          float2& q0, float2& q1)
{
    int a = b >> 1;
    float4 qa = __ldg(t4 + a);
    if (b & 1) {
        float4 qb = __ldg(t4 + a + 1);
        q0 = make_float2(qa.z, qa.w);
        q1 = make_float2(qb.x, qb.y);
    } else {
        q0 = make_float2(qa.x, qa.y);
        q1 = make_float2(qa.z, qa.w);
    }
}

__device__ __forceinline__ float2 interp_one(
    const float4* __restrict__ tab4,
    float px, float py, float pz, int vi, float vf)
{
    float gx = (px + 1.0f) * 0.5f * vf;
    float gy = (py + 1.0f) * 0.5f * vf;
    float gz = (pz + 1.0f) * 0.5f * vf;

    float bxf = floorf(gx), byf = floorf(gy), bzf = floorf(gz);
    float fx = gx - bxf, fy = gy - byf, fz = gz - bzf;

    int ix = (int)bxf, iy = (int)byf, iz = (int)bzf;
    int flat = ix + iy * vi + iz * vi * vi;
    int dz   = vi * vi;

    float2 q000, q100, q010, q110, q001, q101, q011, q111;
    load_pair(tab4, flat,           q000, q100);
    load_pair(tab4, flat + vi,      q010, q110);
    load_pair(tab4, flat + dz,      q001, q101);
    load_pair(tab4, flat + dz + vi, q011, q111);

    float wx0 = 1.0f - fx, wx1 = fx;
    float wy0 = 1.0f - fy, wy1 = fy;
    float wz0 = 1.0f - fz, wz1 = fz;

    float a0x = wx0 * q000.x + wx1 * q100.x;
    float a0y = wx0 * q000.y + wx1 * q100.y;
    float a1x = wx0 * q010.x + wx1 * q110.x;
    float a1y = wx0 * q010.y + wx1 * q110.y;
    float a2x = wx0 * q001.x + wx1 * q101.x;
    float a2y = wx0 * q001.y + wx1 * q101.y;
    float a3x = wx0 * q011.x + wx1 * q111.x;
    float a3y = wx0 * q011.y + wx1 * q111.y;

    float b0x = wy0 * a0x + wy1 * a1x;
    float b0y = wy0 * a0y + wy1 * a1y;
    float b1x = wy0 * a2x + wy1 * a3x;
    float b1y = wy0 * a2y + wy1 * a3y;

    return make_float2(wz0 * b0x + wz1 * b1x,
                       wz0 * b0y + wz1 * b1y);
}

// ---------------- main: block = bin, 9 level-major warps ----------------
__global__ void __launch_bounds__(288) k_main(
    const float* __restrict__ table,
    float* __restrict__ out)
{
    __shared__ float  spx[CAP], spy[CAP], spz[CAP];
    __shared__ int    sid[CAP];
    __shared__ float2 sres[CAP][NUM_LEVELS];
    __shared__ int    sc;

    int b = blockIdx.x;
    int t = threadIdx.x;

    if (t == 0) {
        int raw = g_cnt[b];
        sc = raw < CAP ? raw : CAP;
        g_cnt[b] = 0;                    // reset for next replay
    }
    __syncthreads();
    int c = sc;
    if (c == 0) return;

    if (t < c) {
        float4 f = g_slot[b * CAP + t];  // coalesced
        spx[t] = f.x; spy[t] = f.y; spz[t] = f.z;
        sid[t] = __float_as_int(f.w);
    }
    __syncthreads();

    int w    = t >> 5;                   // warp == level
    int lane = t & 31;
    {
        int   vi = 1 << w;
        float vf = (float)vi;
        const float4* __restrict__ tab4 = (const float4*)table;
        for (int pt = lane; pt < c; pt += 32) {
            sres[pt][w] = interp_one(tab4, spx[pt], spy[pt], spz[pt], vi, vf);
        }
    }
    __syncthreads();

    // write-out: c*9 float2, permuted by original id (72B per point)
    float2* __restrict__ o2 = (float2*)out;
    const float2* s2 = &sres[0][0];
    int total = c * NUM_LEVELS;
    for (int e = t; e < total; e += 288) {
        int pi = e / NUM_LEVELS;
        int li = e - pi * NUM_LEVELS;
        o2[sid[pi] * NUM_LEVELS + li] = s2[e];
    }
}

// ---------------- overflow fallback (normally n == 0) ----------------
__global__ void __launch_bounds__(288) k_over(
    const float* __restrict__ x,
    const float* __restrict__ table,
    float* __restrict__ out)
{
    int n = g_over_cnt;
    int t = threadIdx.x;
    if (n > 0) {
        int w    = t >> 5;
        int lane = t & 31;
        int   vi = 1 << w;
        float vf = (float)vi;
        const float4* __restrict__ tab4 = (const float4*)table;
        float2* __restrict__ o2 = (float2*)out;
        for (int i = lane; i < n; i += 32) {
            int id = g_over_ids[i];
            float2 r = interp_one(tab4, x[id * 3], x[id * 3 + 1], x[id * 3 + 2],
                                  vi, vf);
            o2[id * NUM_LEVELS + w] = r;
        }
    }
    __syncthreads();
    if (t == 0) g_over_cnt = 0;          // reset for next replay
}

extern "C" void kernel_launch(void* const* d_in, const int* in_sizes, int n_in,
                              void* d_out, int out_size)
{
    const float* x     = (const float*)d_in[0];
    const float* table = (const float*)d_in[1];
    float* out         = (float*)d_out;

    int P = in_sizes[0] / 3;
    if (P > PMAX) P = PMAX;

    int binThreads = (P + 3) / 4;
    k_bin<<<(binThreads + 255) / 256, 256>>>((const float4*)x, P);
    k_main<<<NBINS, 288>>>(table, out);
    k_over<<<1, 288>>>(x, table, out);
}

// round 11
// speedup vs baseline: 1.4471x; 1.4471x over previous
#include <cuda_runtime.h>
#include <cuda_bf16.h>
#include <cstdint>

// HashGridEncoding R11: fused spatial binning (hist+scatter in ONE pass,
// 1 pt/thread) + proven R7-shape main (fixed 32-point chunks, one
// interp/thread). Bins = 16^3 = 4096, CAP = 128 (avg 64; overflow prob ~0,
// handled by k_over for unconditional correctness). Resets live in k_over.

#define NUM_LEVELS 9
#define NBINS 4096
#define CAP   128
#define PMAX  262144

__device__ int    g_cnt[NBINS];          // reset by k_over each replay
__device__ float4 g_slot[NBINS * CAP];   // {x, y, z, bitcast(id)}
__device__ int    g_over_cnt;
__device__ int    g_over_ids[PMAX];

// ---------------- pass 1: binning, 1 point/thread ----------------
__global__ void k_bin(const float* __restrict__ x, int P)
{
    int p = blockIdx.x * blockDim.x + threadIdx.x;
    if (p >= P) return;
    float px = x[p * 3 + 0];
    float py = x[p * 3 + 1];
    float pz = x[p * 3 + 2];
    int bx = min(15, max(0, (int)((px + 1.0f) * 8.0f)));
    int by = min(15, max(0, (int)((py + 1.0f) * 8.0f)));
    int bz = min(15, max(0, (int)((pz + 1.0f) * 8.0f)));
    int b  = bx | (by << 4) | (bz << 8);
    int r  = atomicAdd(&g_cnt[b], 1);
    if (r < CAP) {
        g_slot[b * CAP + r] = make_float4(px, py, pz, __int_as_float(p));
    } else {
        int o = atomicAdd(&g_over_cnt, 1);
        g_over_ids[o] = p;
    }
}

// ---------------- interpolation core ----------------
__device__ __forceinline__ void load_pair(const float4* __restrict__ t4, int b,
                                          float2& q0, float2& q1)
{
    int a = b >> 1;
    float4 qa = __ldg(t4 + a);
    if (b & 1) {
        float4 qb = __ldg(t4 + a + 1);
        q0 = make_float2(qa.z, qa.w);
        q1 = make_float2(qb.x, qb.y);
    } else {
        q0 = make_float2(qa.x, qa.y);
        q1 = make_float2(qa.z, qa.w);
    }
}

__device__ __forceinline__ float2 interp_one(
    const float4* __restrict__ tab4,
    float px, float py, float pz, int vi, float vf)
{
    float gx = (px + 1.0f) * 0.5f * vf;
    float gy = (py + 1.0f) * 0.5f * vf;
    float gz = (pz + 1.0f) * 0.5f * vf;

    float bxf = floorf(gx), byf = floorf(gy), bzf = floorf(gz);
    float fx = gx - bxf, fy = gy - byf, fz = gz - bzf;

    int ix = (int)bxf, iy = (int)byf, iz = (int)bzf;
    int flat = ix + iy * vi + iz * vi * vi;
    int dz   = vi * vi;

    float2 q000, q100, q010, q110, q001, q101, q011, q111;
    load_pair(tab4, flat,           q000, q100);
    load_pair(tab4, flat + vi,      q010, q110);
    load_pair(tab4, flat + dz,      q001, q101);
    load_pair(tab4, flat + dz + vi, q011, q111);

    float wx0 = 1.0f - fx, wx1 = fx;
    float wy0 = 1.0f - fy, wy1 = fy;
    float wz0 = 1.0f - fz, wz1 = fz;

    float a0x = wx0 * q000.x + wx1 * q100.x;
    float a0y = wx0 * q000.y + wx1 * q100.y;
    float a1x = wx0 * q010.x + wx1 * q110.x;
    float a1y = wx0 * q010.y + wx1 * q110.y;
    float a2x = wx0 * q001.x + wx1 * q101.x;
    float a2y = wx0 * q001.y + wx1 * q101.y;
    float a3x = wx0 * q011.x + wx1 * q111.x;
    float a3y = wx0 * q011.y + wx1 * q111.y;

    float b0x = wy0 * a0x + wy1 * a1x;
    float b0y = wy0 * a0y + wy1 * a1y;
    float b1x = wy0 * a2x + wy1 * a3x;
    float b1y = wy0 * a2y + wy1 * a3y;

    return make_float2(wz0 * b0x + wz1 * b1x,
                       wz0 * b0y + wz1 * b1y);
}

// ---------------- pass 2: main. block = (bin, 32-point chunk) ----------------
__global__ void __launch_bounds__(288) k_main(
    const float* __restrict__ table,
    float* __restrict__ out)
{
    __shared__ float  spx[32], spy[32], spz[32];
    __shared__ int    sid[32];
    __shared__ float2 sres[32][NUM_LEVELS];

    int bin   = blockIdx.x >> 2;
    int chunk = blockIdx.x & 3;
    int base  = chunk * 32;

    int c = g_cnt[bin];
    if (c > CAP) c = CAP;
    int n = c - base;
    if (n <= 0) return;               // empty chunk: exit immediately
    if (n > 32) n = 32;

    int t = threadIdx.x;
    if (t < n) {
        float4 f = g_slot[bin * CAP + base + t];   // coalesced
        spx[t] = f.x; spy[t] = f.y; spz[t] = f.z;
        sid[t] = __float_as_int(f.w);
    }
    __syncthreads();

    int w    = t >> 5;                 // warp == level (0..8)
    int lane = t & 31;
    if (lane < n) {
        int   vi = 1 << w;
        float vf = (float)vi;
        const float4* __restrict__ tab4 = (const float4*)table;
        sres[lane][w] = interp_one(tab4, spx[lane], spy[lane], spz[lane], vi, vf);
    }
    __syncthreads();

    // write-out: n*9 float2, 72B per point at its original id
    float2* __restrict__ o2 = (float2*)out;
    const float2* s2 = &sres[0][0];
    int total = n * NUM_LEVELS;
    for (int e = t; e < total; e += 288) {
        int pi = e / NUM_LEVELS;
        int li = e - pi * NUM_LEVELS;
        o2[sid[pi] * NUM_LEVELS + li] = s2[e];
    }
}

// ---------------- pass 3: counter reset + overflow fallback ----------------
__global__ void __launch_bounds__(288) k_over(
    const float* __restrict__ x,
    const float* __restrict__ table,
    float* __restrict__ out)
{
    int idx = blockIdx.x * blockDim.x + threadIdx.x;
    if (idx < NBINS) g_cnt[idx] = 0;   // reset for next replay

    if (blockIdx.x == 0) {
        int n = g_over_cnt;            // normally 0
        if (n > 0) {
            int w    = threadIdx.x >> 5;
            int lane = threadIdx.x & 31;
            int   vi = 1 << w;
            float vf = (float)vi;
            const float4* __restrict__ tab4 = (const float4*)table;
            float2* __restrict__ o2 = (float2*)out;
            for (int i = lane; i < n; i += 32) {
                int id = g_over_ids[i];
                float2 r = interp_one(tab4, x[id * 3], x[id * 3 + 1],
                                      x[id * 3 + 2], vi, vf);
                o2[id * NUM_LEVELS + w] = r;
            }
        }
        __syncthreads();
        if (threadIdx.x == 0) g_over_cnt = 0;
    }
}

extern "C" void kernel_launch(void* const* d_in, const int* in_sizes, int n_in,
                              void* d_out, int out_size)
{
    const float* x     = (const float*)d_in[0];
    const float* table = (const float*)d_in[1];
    float* out         = (float*)d_out;

    int P = in_sizes[0] / 3;
    if (P > PMAX) P = PMAX;

    k_bin<<<(P + 255) / 256, 256>>>(x, P);
    k_main<<<NBINS * 4, 288>>>(table, out);
    k_over<<<15, 288>>>(x, table, out);
}

// round 12
// speedup vs baseline: 1.9315x; 1.3348x over previous
#include <cuda_runtime.h>
#include <cuda_bf16.h>
#include <cstdint>

// HashGridEncoding R12: barrier-free pure-warp level-major kernel.
// Global warp W: level = W % 9, points = [ (W/9)*32, +32 ). No smem, no
// __syncthreads -- cheap low-level warps retire immediately instead of
// idling at a block barrier behind l7/l8 warps (R8's L1 util was 74.7%;
// the barrier slack is the target).
//
// Per warp: x-reads coalesced (32 consecutive points, 3 LDG.32 = 3 lines);
// output one STG.64 at stride 72B = 18 lines. Gathers: pair-merged aligned
// LDG.128 (even pair: 1 instr; odd: +1 predicated).

#define NUM_LEVELS 9

__device__ __forceinline__ void load_pair(const float4* __restrict__ t4, int b,
                                          float2& q0, float2& q1)
{
    int a = b >> 1;
    float4 qa = __ldg(t4 + a);
    if (b & 1) {
        float4 qb = __ldg(t4 + a + 1);       // predicated: odd-b lanes only
        q0 = make_float2(qa.z, qa.w);
        q1 = make_float2(qb.x, qb.y);
    } else {
        q0 = make_float2(qa.x, qa.y);
        q1 = make_float2(qa.z, qa.w);
    }
}

__global__ void __launch_bounds__(576) hashgrid_kernel(
    const float* __restrict__ x,
    const float* __restrict__ table,
    float* __restrict__ out,
    int P)
{
    int W    = (blockIdx.x * blockDim.x + threadIdx.x) >> 5;  // global warp id
    int lane = threadIdx.x & 31;

    int w  = W % NUM_LEVELS;            // level
    int pg = W / NUM_LEVELS;            // point group
    int p  = pg * 32 + lane;
    if (p >= P) return;

    // coalesced within warp: 32 consecutive points, stride-3 floats
    float px = __ldg(&x[p * 3 + 0]);
    float py = __ldg(&x[p * 3 + 1]);
    float pz = __ldg(&x[p * 3 + 2]);

    int   vi = 1 << w;
    float vf = (float)vi;

    float gx = (px + 1.0f) * 0.5f * vf;
    float gy = (py + 1.0f) * 0.5f * vf;
    float gz = (pz + 1.0f) * 0.5f * vf;

    float bxf = floorf(gx), byf = floorf(gy), bzf = floorf(gz);
    float fx = gx - bxf, fy = gy - byf, fz = gz - bzf;

    int ix = (int)bxf, iy = (int)byf, iz = (int)bzf;
    int flat = ix + iy * vi + iz * vi * vi;
    int dz   = vi * vi;

    const float4* __restrict__ tab4 = (const float4*)table;

    float2 q000, q100, q010, q110, q001, q101, q011, q111;
    load_pair(tab4, flat,           q000, q100);
    load_pair(tab4, flat + vi,      q010, q110);
    load_pair(tab4, flat + dz,      q001, q101);
    load_pair(tab4, flat + dz + vi, q011, q111);

    float wx0 = 1.0f - fx, wx1 = fx;
    float wy0 = 1.0f - fy, wy1 = fy;
    float wz0 = 1.0f - fz, wz1 = fz;

    float a0x = wx0 * q000.x + wx1 * q100.x;
    float a0y = wx0 * q000.y + wx1 * q100.y;
    float a1x = wx0 * q010.x + wx1 * q110.x;
    float a1y = wx0 * q010.y + wx1 * q110.y;
    float a2x = wx0 * q001.x + wx1 * q101.x;
    float a2y = wx0 * q001.y + wx1 * q101.y;
    float a3x = wx0 * q011.x + wx1 * q111.x;
    float a3y = wx0 * q011.y + wx1 * q111.y;

    float b0x = wy0 * a0x + wy1 * a1x;
    float b0y = wy0 * a0y + wy1 * a1y;
    float b1x = wy0 * a2x + wy1 * a3x;
    float b1y = wy0 * a2y + wy1 * a3y;

    float rx = wz0 * b0x + wz1 * b1x;
    float ry = wz0 * b0y + wz1 * b1y;

    // one STG.64 per lane; warp covers 32 points at level w: 18 lines
    float2* __restrict__ o2 = (float2*)out;
    o2[p * NUM_LEVELS + w] = make_float2(rx, ry);
}

extern "C" void kernel_launch(void* const* d_in, const int* in_sizes, int n_in,
                              void* d_out, int out_size)
{
    const float* x     = (const float*)d_in[0];
    const float* table = (const float*)d_in[1];
    float* out         = (float*)d_out;

    int P = in_sizes[0] / 3;
    int pgroups = (P + 31) / 32;
    long long totalThreads = (long long)pgroups * NUM_LEVELS * 32;
    int threads = 576;                              // 18 warps = 2 point-groups
    int blocks = (int)((totalThreads + threads - 1) / threads);
    hashgrid_kernel<<<blocks, threads>>>(x, table, out, P);
}

// round 13
// speedup vs baseline: 2.0306x; 1.0513x over previous
#include <cuda_runtime.h>
#include <cuda_bf16.h>
#include <cstdint>

// HashGridEncoding R13: R8 skeleton (staged x, staged coalesced output,
// 32 pts / 288-thread block) + LEVEL-PAIRED HALF-WARPS for perfect warp
// balance: warp k lanes 0-15 -> level k, pts 0-15; lanes 16-31 -> level 8-k,
// pts 16-31. Every warp's gather work = (W(k)+W(8-k))/2 == equal, so the
// block barriers no longer wait on a single heavy level-8 warp (R8's L1 was
// 74.7% busy; imbalance slack is the target).

#define NUM_LEVELS 9

__device__ __forceinline__ void load_pair(const float4* __restrict__ t4, int b,
                                          float2& q0, float2& q1)
{
    int a = b >> 1;
    float4 qa = __ldg(t4 + a);
    if (b & 1) {
        float4 qb = __ldg(t4 + a + 1);       // predicated: odd-b lanes only
        q0 = make_float2(qa.z, qa.w);
        q1 = make_float2(qb.x, qb.y);
    } else {
        q0 = make_float2(qa.x, qa.y);
        q1 = make_float2(qa.z, qa.w);
    }
}

__global__ void __launch_bounds__(288) hashgrid_kernel(
    const float* __restrict__ x,
    const float* __restrict__ table,
    float* __restrict__ out,
    int P)
{
    __shared__ float  sx[96];                  // 32 points x 3 coords
    __shared__ float2 sres[32][NUM_LEVELS];

    int pbase = blockIdx.x * 32;
    int t = threadIdx.x;

    if (t < 96) {
        int g = pbase * 3 + t;
        sx[t] = (g < P * 3) ? x[g] : 0.0f;
    }
    __syncthreads();

    int k    = t >> 5;                  // warp id (0..8)
    int lane = t & 31;

    // level-paired mapping: lanes 0-15 -> level k, lanes 16-31 -> level 8-k;
    // point index == lane in both halves.
    int lvl = (lane < 16) ? k : (8 - k);
    int pt  = lane;

    {
        int   vi = 1 << lvl;
        float vf = (float)vi;

        float gx = (sx[pt * 3 + 0] + 1.0f) * 0.5f * vf;
        float gy = (sx[pt * 3 + 1] + 1.0f) * 0.5f * vf;
        float gz = (sx[pt * 3 + 2] + 1.0f) * 0.5f * vf;

        float bxf = floorf(gx), byf = floorf(gy), bzf = floorf(gz);
        float fx = gx - bxf, fy = gy - byf, fz = gz - bzf;

        int ix = (int)bxf, iy = (int)byf, iz = (int)bzf;
        int flat = ix + iy * vi + iz * vi * vi;
        int dz   = vi * vi;

        const float4* __restrict__ tab4 = (const float4*)table;

        float2 q000, q100, q010, q110, q001, q101, q011, q111;
        load_pair(tab4, flat,           q000, q100);
        load_pair(tab4, flat + vi,      q010, q110);
        load_pair(tab4, flat + dz,      q001, q101);
        load_pair(tab4, flat + dz + vi, q011, q111);

        float wx0 = 1.0f - fx, wx1 = fx;
        float wy0 = 1.0f - fy, wy1 = fy;
        float wz0 = 1.0f - fz, wz1 = fz;

        float a0x = wx0 * q000.x + wx1 * q100.x;
        float a0y = wx0 * q000.y + wx1 * q100.y;
        float a1x = wx0 * q010.x + wx1 * q110.x;
        float a1y = wx0 * q010.y + wx1 * q110.y;
        float a2x = wx0 * q001.x + wx1 * q101.x;
        float a2y = wx0 * q001.y + wx1 * q101.y;
        float a3x = wx0 * q011.x + wx1 * q111.x;
        float a3y = wx0 * q011.y + wx1 * q111.y;

        float b0x = wy0 * a0x + wy1 * a1x;
        float b0y = wy0 * a0y + wy1 * a1y;
        float b1x = wy0 * a2x + wy1 * a3x;
        float b1y = wy0 * a2y + wy1 * a3y;

        sres[pt][lvl] = make_float2(wz0 * b0x + wz1 * b1x,
                                    wz0 * b0y + wz1 * b1y);
    }
    __syncthreads();

    // write-out: 288 float2 = 32 points x 9 levels, fully coalesced 2304B
    int pi = t / NUM_LEVELS;
    int li = t - pi * NUM_LEVELS;
    int p  = pbase + pi;
    if (p < P) {
        float2* __restrict__ o2 = (float2*)out;
        o2[p * NUM_LEVELS + li] = sres[pi][li];
    }
}

extern "C" void kernel_launch(void* const* d_in, const int* in_sizes, int n_in,
                              void* d_out, int out_size)
{
    const float* x     = (const float*)d_in[0];
    const float* table = (const float*)d_in[1];
    float* out         = (float*)d_out;

    int P = in_sizes[0] / 3;
    int blocks = (P + 31) / 32;        // 32 points per block, 9 warps
    hashgrid_kernel<<<blocks, 288>>>(x, table, out, P);
}